// round 3
// baseline (speedup 1.0000x reference)
#include <cuda_runtime.h>
#include <cstdint>

#define E_TOT  (256*4096)   // 1048576 edges
#define NNODE  (256*512)    // 131072 nodes
#define DHID   64
#define BNUM   256
#define EPB    4096
#define NPB    512
#define KKEEP  1024
#define KDROP  3072

// ---- scratch (device globals: allocation-free rule) ----
__device__ float g_scores[E_TOT];
__device__ unsigned char g_mask[NNODE];

__device__ __forceinline__ unsigned long long pk2(float x, float y) {
    unsigned long long r;
    asm("mov.b64 %0, {%1, %2};" : "=l"(r) : "f"(x), "f"(y));
    return r;
}
__device__ __forceinline__ void fma2(unsigned long long& d,
                                     unsigned long long a, unsigned long long b) {
    asm("fma.rn.f32x2 %0, %1, %2, %0;" : "+l"(d) : "l"(a), "l"(b));
}

// ---------------------------------------------------------------------------
// K0: zero the node mask (graph replays must be idempotent)
// ---------------------------------------------------------------------------
__global__ void k0_zero() {
    int i = blockIdx.x * blockDim.x + threadIdx.x;
    ((unsigned int*)g_mask)[i] = 0u;
}

// ---------------------------------------------------------------------------
// K12: fused per-batch MLP edge scorer.
//  - h_batch (512x64) staged once in SMEM (pad 68 -> conflict-free strided reads)
//  - hidden dim in 64 chunks of 4 cols (A and B simultaneously)
//  - warps 0-3: f32x2 GEMM producers (4 nodes x 4 pairs each, double-buffered out)
//  - warps 4-15: edge consumers (chunk c-1 while producers build chunk c)
//  - plain __syncthreads per chunk gives the producer/consumer handoff
// ---------------------------------------------------------------------------
__global__ void __launch_bounds__(512) k12(const float* __restrict__ hmat,
                                           const float* __restrict__ W1,
                                           const float* __restrict__ b1,
                                           const float* __restrict__ W2,
                                           const float* __restrict__ b2p,
                                           const int*   __restrict__ ei) {
    extern __shared__ float sm[];
    float* hsm = sm;                          // [512][68]
    float* AsB = sm + 512 * 68;               // [2][512][4]
    float* BsB = AsB + 2 * 512 * 4;           // [2][512][4]
    float* Wb  = BsB + 2 * 512 * 4;           // [2][64][8]  (A 4 cols | B 4 cols)
    float* w2s = Wb + 2 * 64 * 8;             // [256]
    float* b1s = w2s + 256;                   // [256]

    const int tid  = threadIdx.x;
    const bool prod = (tid < 128);
    const int ctid = tid - 128;
    const int b    = blockIdx.x;

    if (tid < 64)       *(float4*)(w2s + tid * 4)        = *(const float4*)(W2 + tid * 4);
    else if (tid < 128) *(float4*)(b1s + (tid - 64) * 4) = *(const float4*)(b1 + (tid - 64) * 4);

    // stage h batch (coalesced)
    const float* hb = hmat + (size_t)b * NPB * 64;
    for (int i = tid; i < 512 * 16; i += 512) {
        int n = i >> 4, c4 = i & 15;
        *(float4*)(hsm + n * 68 + c4 * 4) = *(const float4*)(hb + n * 64 + c4 * 4);
    }
    // stage W chunk 0 into Wb[0]
    if (prod) {
        int k = tid >> 1, q = tid & 1;
        const float* src = (q == 0) ? (W1 + k * 256) : (W1 + (64 + k) * 256);
        *(float4*)(Wb + k * 8 + q * 4) = *(const float4*)src;
    }

    // consumers: load edge endpoints (11 edges/thread, last one ragged)
    int rowi[11], coli[11];
    float acc[11];
    if (!prod) {
        #pragma unroll
        for (int i = 0; i < 11; ++i) {
            int e = ctid + 384 * i;
            if (e < EPB) {
                rowi[i] = (ei[b * EPB + e]         - b * NPB) * 4;
                coli[i] = (ei[E_TOT + b * EPB + e] - b * NPB) * 4;
            } else { rowi[i] = 0; coli[i] = 0; }
            acc[i] = 0.f;
        }
    }
    __syncthreads();

    for (int c = 0; c <= 64; ++c) {
        if (prod) {
            if (c < 64) {
                const int cb = c & 1;
                const float* Wr = Wb + cb * 512;
                float4 bi = *(const float4*)(b1s + c * 4);
                unsigned long long aA[4][2], aB[4][2];
                unsigned long long i0 = pk2(bi.x, bi.y), i1 = pk2(bi.z, bi.w);
                #pragma unroll
                for (int i = 0; i < 4; ++i) {
                    aA[i][0] = i0; aA[i][1] = i1;
                    aB[i][0] = 0ull; aB[i][1] = 0ull;
                }
                #pragma unroll 4
                for (int k4 = 0; k4 < 16; ++k4) {
                    float4 hv[4];
                    #pragma unroll
                    for (int i = 0; i < 4; ++i)
                        hv[i] = *(const float4*)(hsm + (tid + 128 * i) * 68 + k4 * 4);
                    #pragma unroll
                    for (int kk = 0; kk < 4; ++kk) {
                        const float* wr = Wr + (k4 * 4 + kk) * 8;
                        ulonglong2 wA = *(const ulonglong2*)wr;
                        ulonglong2 wB = *(const ulonglong2*)(wr + 4);
                        #pragma unroll
                        for (int i = 0; i < 4; ++i) {
                            float h = (kk == 0) ? hv[i].x : (kk == 1) ? hv[i].y
                                    : (kk == 2) ? hv[i].z : hv[i].w;
                            unsigned long long h2 = pk2(h, h);
                            fma2(aA[i][0], h2, wA.x); fma2(aA[i][1], h2, wA.y);
                            fma2(aB[i][0], h2, wB.x); fma2(aB[i][1], h2, wB.y);
                        }
                    }
                }
                #pragma unroll
                for (int i = 0; i < 4; ++i) {
                    int n = tid + 128 * i;
                    ulonglong2 va; va.x = aA[i][0]; va.y = aA[i][1];
                    ulonglong2 vb; vb.x = aB[i][0]; vb.y = aB[i][1];
                    *(ulonglong2*)(AsB + cb * 2048 + n * 4) = va;
                    *(ulonglong2*)(BsB + cb * 2048 + n * 4) = vb;
                }
                // stage W for chunk c+1 (visible after the barrier below)
                if (c + 1 < 64) {
                    int k = tid >> 1, q = tid & 1;
                    const float* src = (q == 0) ? (W1 + k * 256 + (c + 1) * 4)
                                                : (W1 + (64 + k) * 256 + (c + 1) * 4);
                    *(float4*)(Wb + ((c + 1) & 1) * 512 + k * 8 + q * 4) = *(const float4*)src;
                }
            }
        } else if (c >= 1) {
            const int cb = (c - 1) & 1;
            const float4 w2v = *(const float4*)(w2s + (c - 1) * 4);
            const float* Ab = AsB + cb * 2048;
            const float* Bb = BsB + cb * 2048;
            #pragma unroll
            for (int i = 0; i < 11; ++i) {
                float4 av = *(const float4*)(Ab + rowi[i]);
                float4 bv = *(const float4*)(Bb + coli[i]);
                float s = acc[i];
                s = fmaf(fmaxf(av.x + bv.x, 0.f), w2v.x, s);
                s = fmaf(fmaxf(av.y + bv.y, 0.f), w2v.y, s);
                s = fmaf(fmaxf(av.z + bv.z, 0.f), w2v.z, s);
                s = fmaf(fmaxf(av.w + bv.w, 0.f), w2v.w, s);
                acc[i] = s;
            }
        }
        __syncthreads();
    }

    if (!prod) {
        const float b2v = b2p[0];
        #pragma unroll
        for (int i = 0; i < 11; ++i) {
            int e = ctid + 384 * i;
            if (e < EPB) g_scores[b * EPB + e] = acc[i] + b2v;
        }
    }
}

// ---------------------------------------------------------------------------
// K3: hybrid bitonic argsort (4096 keys, 4/thread in registers).
// ---------------------------------------------------------------------------
__global__ void __launch_bounds__(1024) k3_sort(const int* __restrict__ ei,
                                                float* __restrict__ out) {
    __shared__ unsigned long long sk[4096];
    const int b = blockIdx.x, tid = threadIdx.x;

    unsigned long long key[4];
    float4 sc = *(const float4*)(g_scores + b * EPB + tid * 4);
    float sv[4] = {sc.x, sc.y, sc.z, sc.w};
    #pragma unroll
    for (int r = 0; r < 4; ++r) {
        unsigned int u = __float_as_uint(sv[r]);
        unsigned int enc = (u & 0x80000000u) ? ~u : (u | 0x80000000u);
        key[r] = ((unsigned long long)(~enc) << 32) | (unsigned int)(tid * 4 + r);
    }

    for (int k = 2; k <= 4096; k <<= 1) {
        int j = k >> 1;
        for (; j >= 128; j >>= 1) {
            #pragma unroll
            for (int r = 0; r < 4; ++r) sk[tid * 4 + r] = key[r];
            __syncthreads();
            #pragma unroll
            for (int r = 0; r < 4; ++r) {
                int i = tid * 4 + r;
                unsigned long long pk = sk[i ^ j];
                bool up = ((i & k) == 0);
                bool lo = ((i & j) == 0);
                unsigned long long mn = key[r] < pk ? key[r] : pk;
                unsigned long long mx = key[r] < pk ? pk : key[r];
                key[r] = (lo == up) ? mn : mx;
            }
            __syncthreads();
        }
        for (; j >= 4; j >>= 1) {
            int lm = j >> 2;
            #pragma unroll
            for (int r = 0; r < 4; ++r) {
                unsigned long long pk = __shfl_xor_sync(0xffffffffu, key[r], lm);
                int i = tid * 4 + r;
                bool up = ((i & k) == 0);
                bool lo = ((i & j) == 0);
                unsigned long long mn = key[r] < pk ? key[r] : pk;
                unsigned long long mx = key[r] < pk ? pk : key[r];
                key[r] = (lo == up) ? mn : mx;
            }
        }
        if (k >= 4) {
            #pragma unroll
            for (int r = 0; r < 2; ++r) {
                int i = tid * 4 + r;
                bool up = ((i & k) == 0);
                unsigned long long a = key[r], c2 = key[r + 2];
                unsigned long long mn = a < c2 ? a : c2;
                unsigned long long mx = a < c2 ? c2 : a;
                key[r]     = up ? mn : mx;
                key[r + 2] = up ? mx : mn;
            }
        }
        #pragma unroll
        for (int p = 0; p < 2; ++p) {
            int r0 = p * 2;
            int i = tid * 4 + r0;
            bool up = ((i & k) == 0);
            unsigned long long a = key[r0], c2 = key[r0 + 1];
            unsigned long long mn = a < c2 ? a : c2;
            unsigned long long mx = a < c2 ? c2 : a;
            key[r0]     = up ? mn : mx;
            key[r0 + 1] = up ? mx : mn;
        }
    }

    const int obase_keep = BNUM * DHID;
    const int obase_spu  = obase_keep + BNUM * KKEEP;
    #pragma unroll
    for (int r = 0; r < 4; ++r) {
        int pos = tid * 4 + r;
        unsigned long long kv = key[r];
        unsigned int enc = ~(unsigned int)(kv >> 32);
        unsigned int bits = (enc & 0x80000000u) ? (enc ^ 0x80000000u) : ~enc;
        float s = __uint_as_float(bits);
        int idx = (int)(unsigned int)(kv & 0xFFFFFFFFu);
        if (pos < KKEEP) {
            out[obase_keep + b * KKEEP + pos] = s;
            int g = b * EPB + idx;
            g_mask[ei[g]] = 1;
            g_mask[ei[E_TOT + g]] = 1;
        } else {
            out[obase_spu + b * KDROP + (pos - KKEEP)] = -s;
        }
    }
}

// ---------------------------------------------------------------------------
// K4: causal_rep[b] = sum of h rows for masked nodes of batch b
// ---------------------------------------------------------------------------
__global__ void __launch_bounds__(256) k4_rep(const float* __restrict__ hmat,
                                              float* __restrict__ out) {
    __shared__ float red[4][64];
    const int b = blockIdx.x, tid = threadIdx.x;
    const int d = tid & 63, q = tid >> 6;
    const int nb = b * NPB;
    float s = 0.f;
    for (int n = q; n < NPB; n += 4) {
        if (g_mask[nb + n]) s += hmat[(size_t)(nb + n) * 64 + d];
    }
    red[q][d] = s;
    __syncthreads();
    if (tid < 64)
        out[b * 64 + tid] = red[0][tid] + red[1][tid] + red[2][tid] + red[3][tid];
}

// ---------------------------------------------------------------------------
extern "C" void kernel_launch(void* const* d_in, const int* in_sizes, int n_in,
                              void* d_out, int out_size) {
    const float* hmat = (const float*)d_in[0];
    const float* W1   = (const float*)d_in[1];
    const float* b1   = (const float*)d_in[2];
    const float* W2   = (const float*)d_in[3];
    const float* b2   = (const float*)d_in[4];
    const int*   ei   = (const int*)  d_in[5];
    float* out = (float*)d_out;

    const int smem12 = (512 * 68 + 2 * 512 * 4 * 2 + 2 * 64 * 8 + 512) * 4; // 178176 B
    cudaFuncSetAttribute(k12, cudaFuncAttributeMaxDynamicSharedMemorySize, smem12);

    k0_zero<<<32, 1024>>>();
    k12<<<BNUM, 512, smem12>>>(hmat, W1, b1, W2, b2, ei);
    k3_sort<<<BNUM, 1024>>>(ei, out);
    k4_rep<<<BNUM, 256>>>(hmat, out);
}

// round 4
// speedup vs baseline: 1.7035x; 1.7035x over previous
#include <cuda_runtime.h>
#include <cstdint>

#define E_TOT  (256*4096)   // 1048576 edges
#define NNODE  (256*512)    // 131072 nodes
#define DHID   64
#define BNUM   256
#define EPB    4096
#define NPB    512
#define KKEEP  1024
#define KDROP  3072

// chunk-major AB: [batch][chunk 0..127][node 0..511][4 floats]
// chunks 0..63 = A (cols 0..255), 64..127 = B (cols 256..511)
__device__ float g_AB[(size_t)BNUM * 128 * 512 * 4];
__device__ float g_scores[E_TOT];
__device__ unsigned char g_mask[NNODE];

__device__ __forceinline__ unsigned long long pk2(float x, float y) {
    unsigned long long r;
    asm("mov.b64 %0, {%1, %2};" : "=l"(r) : "f"(x), "f"(y));
    return r;
}
__device__ __forceinline__ void fma2(unsigned long long& d,
                                     unsigned long long a, unsigned long long b) {
    asm("fma.rn.f32x2 %0, %1, %2, %0;" : "+l"(d) : "l"(a), "l"(b));
}

// ---------------------------------------------------------------------------
// K0: zero node mask
// ---------------------------------------------------------------------------
__global__ void k0_zero() {
    int i = blockIdx.x * blockDim.x + threadIdx.x;
    ((unsigned int*)g_mask)[i] = 0u;
}

// ---------------------------------------------------------------------------
// K1: AB = h @ Wc, CTA = 64 rows x 256 cols (half). 2 CTAs/SM.
// Output staged through SMEM -> chunk-major coalesced STG.
// ---------------------------------------------------------------------------
__global__ void __launch_bounds__(256) k1_gemm(const float* __restrict__ hmat,
                                               const float* __restrict__ W1) {
    extern __shared__ float sm1[];
    float* Ws = sm1;              // [64][256]
    float* hs = sm1 + 64 * 256;   // [64][65]
    const int tid  = threadIdx.x;
    const int tile = blockIdx.x >> 1;
    const int half = blockIdx.x & 1;          // 0 = A (W1 top), 1 = B (W1 bottom)
    const int rowbase = tile * 64;
    const int b     = rowbase >> 9;
    const int nboff = rowbase & 511;

    for (int i = tid; i < 64 * 64; i += 256) {
        int k = i >> 6, o4 = i & 63;
        *(float4*)(Ws + k * 256 + o4 * 4) =
            *(const float4*)(W1 + (size_t)(half * 64 + k) * 256 + o4 * 4);
    }
    for (int i = tid; i < 64 * 16; i += 256) {
        int n = i >> 4, k4 = i & 15;
        float4 v = *(const float4*)(hmat + (size_t)(rowbase + n) * 64 + k4 * 4);
        hs[(k4 * 4 + 0) * 65 + n] = v.x;
        hs[(k4 * 4 + 1) * 65 + n] = v.y;
        hs[(k4 * 4 + 2) * 65 + n] = v.z;
        hs[(k4 * 4 + 3) * 65 + n] = v.w;
    }
    __syncthreads();

    const int w = tid >> 5, l = tid & 31;
    const int r0 = w * 8;

    unsigned long long acc[8][4];
    #pragma unroll
    for (int i = 0; i < 8; ++i)
        #pragma unroll
        for (int p = 0; p < 4; ++p) acc[i][p] = 0ull;

    #pragma unroll 4
    for (int k = 0; k < 64; ++k) {
        ulonglong2 b0 = *(const ulonglong2*)(Ws + k * 256 + 4 * l);        // cols 4l..4l+3
        ulonglong2 b1 = *(const ulonglong2*)(Ws + k * 256 + 128 + 4 * l);  // cols 128+4l..
        #pragma unroll
        for (int i = 0; i < 8; ++i) {
            unsigned int au = __float_as_uint(hs[k * 65 + r0 + i]);  // broadcast
            unsigned long long a2;
            asm("mov.b64 %0, {%1, %1};" : "=l"(a2) : "r"(au));
            fma2(acc[i][0], a2, b0.x); fma2(acc[i][1], a2, b0.y);
            fma2(acc[i][2], a2, b1.x); fma2(acc[i][3], a2, b1.y);
        }
    }

    // stage to SMEM in [cc][node] float4 (pad 65) then coalesced chunk-major STG
    __syncthreads();
    float4* st = (float4*)sm1;    // [64][65] float4 = 66.6 KB (fits in 82 KB)
    #pragma unroll
    for (int i = 0; i < 8; ++i) {
        int node = r0 + i;
        float4 v0, v1;
        *(unsigned long long*)&v0.x = acc[i][0];
        *(unsigned long long*)&v0.z = acc[i][1];
        *(unsigned long long*)&v1.x = acc[i][2];
        *(unsigned long long*)&v1.z = acc[i][3];
        st[l * 65 + node]        = v0;   // cc = l
        st[(32 + l) * 65 + node] = v1;   // cc = 32 + l
    }
    __syncthreads();

    float4* dst = (float4*)g_AB;
    #pragma unroll
    for (int j = 0; j < 16; ++j) {
        int idx = tid + j * 256;              // 0..4095
        int cc = idx >> 6, node = idx & 63;
        size_t cg = (size_t)b * 128 + half * 64 + cc;
        dst[cg * 512 + nboff + node] = st[cc * 65 + node];
    }
}

// ---------------------------------------------------------------------------
// K2: edge scores, chunk-4 streaming. 2 CTAs/batch (2048 edges each).
// Coalesced chunk-major LDG, reg-double-buffered, one barrier/chunk.
// ---------------------------------------------------------------------------
__global__ void __launch_bounds__(512) k2_edges(const float* __restrict__ b1,
                                                const float* __restrict__ W2,
                                                const float* __restrict__ b2p,
                                                const int*   __restrict__ ei) {
    __shared__ float As[2][512 * 4];
    __shared__ float Bs[2][512 * 4];
    __shared__ float w2s[256];
    __shared__ float b1s[256];
    const int tid = threadIdx.x;
    const int b   = blockIdx.x >> 1;
    const int eh  = blockIdx.x & 1;
    const int ebase = b * EPB + eh * 2048;

    if (tid < 64)       *(float4*)(w2s + tid * 4)        = *(const float4*)(W2 + tid * 4);
    else if (tid < 128) *(float4*)(b1s + (tid - 64) * 4) = *(const float4*)(b1 + (tid - 64) * 4);

    int roff[4], coff[4];
    float acc[4];
    #pragma unroll
    for (int i = 0; i < 4; ++i) {
        int e = ebase + tid + i * 512;
        roff[i] = (ei[e]         - b * NPB) * 4;
        coff[i] = (ei[E_TOT + e] - b * NPB) * 4;
        acc[i] = 0.f;
    }

    const float4* gA = (const float4*)g_AB + (size_t)b * 128 * 512;
    float4 ra = gA[(size_t)0  * 512 + tid];        // chunk 0 (A)
    float4 rb = gA[(size_t)64 * 512 + tid];        // chunk 64 (B)
    __syncthreads();

    for (int c = 0; c < 64; ++c) {
        const int buf = c & 1;
        float4 bv = *(const float4*)(b1s + c * 4);
        float4 wa;
        wa.x = ra.x + bv.x; wa.y = ra.y + bv.y;
        wa.z = ra.z + bv.z; wa.w = ra.w + bv.w;
        *(float4*)(As[buf] + tid * 4) = wa;
        *(float4*)(Bs[buf] + tid * 4) = rb;
        __syncthreads();
        if (c + 1 < 64) {
            ra = gA[(size_t)(c + 1)  * 512 + tid];
            rb = gA[(size_t)(c + 65) * 512 + tid];
        }
        const float4 w2v = *(const float4*)(w2s + c * 4);
        const float* Ab = As[buf];
        const float* Bb = Bs[buf];
        #pragma unroll
        for (int i = 0; i < 4; ++i) {
            float4 av = *(const float4*)(Ab + roff[i]);
            float4 b4 = *(const float4*)(Bb + coff[i]);
            float s = acc[i];
            s = fmaf(fmaxf(av.x + b4.x, 0.f), w2v.x, s);
            s = fmaf(fmaxf(av.y + b4.y, 0.f), w2v.y, s);
            s = fmaf(fmaxf(av.z + b4.z, 0.f), w2v.z, s);
            s = fmaf(fmaxf(av.w + b4.w, 0.f), w2v.w, s);
            acc[i] = s;
        }
    }
    const float b2v = b2p[0];
    #pragma unroll
    for (int i = 0; i < 4; ++i)
        g_scores[ebase + tid + i * 512] = acc[i] + b2v;
}

// ---------------------------------------------------------------------------
// K3: hybrid bitonic argsort (4096 keys, 4/thread).
// ---------------------------------------------------------------------------
__global__ void __launch_bounds__(1024) k3_sort(const int* __restrict__ ei,
                                                float* __restrict__ out) {
    __shared__ unsigned long long sk[4096];
    const int b = blockIdx.x, tid = threadIdx.x;

    unsigned long long key[4];
    float4 sc = *(const float4*)(g_scores + b * EPB + tid * 4);
    float sv[4] = {sc.x, sc.y, sc.z, sc.w};
    #pragma unroll
    for (int r = 0; r < 4; ++r) {
        unsigned int u = __float_as_uint(sv[r]);
        unsigned int enc = (u & 0x80000000u) ? ~u : (u | 0x80000000u);
        key[r] = ((unsigned long long)(~enc) << 32) | (unsigned int)(tid * 4 + r);
    }

    for (int k = 2; k <= 4096; k <<= 1) {
        int j = k >> 1;
        for (; j >= 128; j >>= 1) {
            #pragma unroll
            for (int r = 0; r < 4; ++r) sk[tid * 4 + r] = key[r];
            __syncthreads();
            #pragma unroll
            for (int r = 0; r < 4; ++r) {
                int i = tid * 4 + r;
                unsigned long long pk = sk[i ^ j];
                bool up = ((i & k) == 0);
                bool lo = ((i & j) == 0);
                unsigned long long mn = key[r] < pk ? key[r] : pk;
                unsigned long long mx = key[r] < pk ? pk : key[r];
                key[r] = (lo == up) ? mn : mx;
            }
            __syncthreads();
        }
        for (; j >= 4; j >>= 1) {
            int lm = j >> 2;
            #pragma unroll
            for (int r = 0; r < 4; ++r) {
                unsigned long long pk = __shfl_xor_sync(0xffffffffu, key[r], lm);
                int i = tid * 4 + r;
                bool up = ((i & k) == 0);
                bool lo = ((i & j) == 0);
                unsigned long long mn = key[r] < pk ? key[r] : pk;
                unsigned long long mx = key[r] < pk ? pk : key[r];
                key[r] = (lo == up) ? mn : mx;
            }
        }
        if (k >= 4) {
            #pragma unroll
            for (int r = 0; r < 2; ++r) {
                int i = tid * 4 + r;
                bool up = ((i & k) == 0);
                unsigned long long a = key[r], c2 = key[r + 2];
                unsigned long long mn = a < c2 ? a : c2;
                unsigned long long mx = a < c2 ? c2 : a;
                key[r]     = up ? mn : mx;
                key[r + 2] = up ? mx : mn;
            }
        }
        #pragma unroll
        for (int p = 0; p < 2; ++p) {
            int r0 = p * 2;
            int i = tid * 4 + r0;
            bool up = ((i & k) == 0);
            unsigned long long a = key[r0], c2 = key[r0 + 1];
            unsigned long long mn = a < c2 ? a : c2;
            unsigned long long mx = a < c2 ? c2 : a;
            key[r0]     = up ? mn : mx;
            key[r0 + 1] = up ? mx : mn;
        }
    }

    const int obase_keep = BNUM * DHID;
    const int obase_spu  = obase_keep + BNUM * KKEEP;
    #pragma unroll
    for (int r = 0; r < 4; ++r) {
        int pos = tid * 4 + r;
        unsigned long long kv = key[r];
        unsigned int enc = ~(unsigned int)(kv >> 32);
        unsigned int bits = (enc & 0x80000000u) ? (enc ^ 0x80000000u) : ~enc;
        float s = __uint_as_float(bits);
        int idx = (int)(unsigned int)(kv & 0xFFFFFFFFu);
        if (pos < KKEEP) {
            out[obase_keep + b * KKEEP + pos] = s;
            int g = b * EPB + idx;
            g_mask[ei[g]] = 1;
            g_mask[ei[E_TOT + g]] = 1;
        } else {
            out[obase_spu + b * KDROP + (pos - KKEEP)] = -s;
        }
    }
}

// ---------------------------------------------------------------------------
// K4: masked per-batch sum of h rows (mask as fp multiplier, MLP-friendly)
// ---------------------------------------------------------------------------
__global__ void __launch_bounds__(512) k4_rep(const float* __restrict__ hmat,
                                              float* __restrict__ out) {
    __shared__ float red[8][64];
    const int b = blockIdx.x, tid = threadIdx.x;
    const int d = tid & 63, q = tid >> 6;      // q in 0..7
    const int nb = b * NPB;
    float s0 = 0.f, s1 = 0.f;
    #pragma unroll 4
    for (int n = q; n < NPB; n += 16) {
        float m0 = (float)g_mask[nb + n];
        float m1 = (float)g_mask[nb + n + 8];
        s0 = fmaf(m0, hmat[(size_t)(nb + n) * 64 + d], s0);
        s1 = fmaf(m1, hmat[(size_t)(nb + n + 8) * 64 + d], s1);
    }
    red[q][d] = s0 + s1;
    __syncthreads();
    if (tid < 64) {
        float t = 0.f;
        #pragma unroll
        for (int qq = 0; qq < 8; ++qq) t += red[qq][tid];
        out[b * 64 + tid] = t;
    }
}

// ---------------------------------------------------------------------------
extern "C" void kernel_launch(void* const* d_in, const int* in_sizes, int n_in,
                              void* d_out, int out_size) {
    const float* hmat = (const float*)d_in[0];
    const float* W1   = (const float*)d_in[1];
    const float* b1   = (const float*)d_in[2];
    const float* W2   = (const float*)d_in[3];
    const float* b2   = (const float*)d_in[4];
    const int*   ei   = (const int*)  d_in[5];
    float* out = (float*)d_out;

    const int smem1 = (64 * 256 + 64 * 65) * 4;   // 82176 B -> 2 CTAs/SM
    cudaFuncSetAttribute(k1_gemm, cudaFuncAttributeMaxDynamicSharedMemorySize, smem1);

    k0_zero<<<32, 1024>>>();
    k1_gemm<<<4096, 256, smem1>>>(hmat, W1);
    k2_edges<<<BNUM * 2, 512>>>(b1, W2, b2, ei);
    k3_sort<<<BNUM, 1024>>>(ei, out);
    k4_rep<<<BNUM, 512>>>(hmat, out);
}